// round 2
// baseline (speedup 1.0000x reference)
#include <cuda_runtime.h>
#include <math.h>

#define B_ 1024
#define D_ 1024
#define H_ 4096
#define C_ 5120
#define LN_EPS 1e-3f

// ---------------- scratch (device globals: allocation-free) ----------------
__device__ float g_u  [B_ * H_];   // sigmoid(update gate)
__device__ float g_rh [B_ * H_];   // r * h
__device__ float g_sg [B_ * H_];   // silu(gate)
__device__ float g_up [B_ * H_];   // up projection
__device__ float g_nh [B_ * H_];   // new_h fallback (if out buffer only holds `out`)
__device__ float g_do [B_ * D_];   // pre-LN down projection

// ---------------- packed f32x2 helpers ----------------
__device__ __forceinline__ unsigned long long pack2(float lo, float hi) {
    unsigned long long r;
    asm("mov.b64 %0, {%1, %2};" : "=l"(r) : "f"(lo), "f"(hi));
    return r;
}
__device__ __forceinline__ void fma2(unsigned long long& d, unsigned long long a, unsigned long long b) {
    asm("fma.rn.f32x2 %0, %1, %2, %0;" : "+l"(d) : "l"(a), "l"(b));
}
__device__ __forceinline__ float2 unpack2(unsigned long long v) {
    float2 f;
    asm("mov.b64 {%0, %1}, %2;" : "=f"(f.x), "=f"(f.y) : "l"(v));
    return f;
}
__device__ __forceinline__ float sigmoidf(float x) {
    return 1.0f / (1.0f + expf(-x));
}

// ---------------- generic fused SGEMM ----------------
// C[B, N] = Aconcat[B, K] @ W[K, N] + bias, epilogue by mode.
// Aconcat column k: k < K1 -> A1[row*lda1 + k], else A2[row*lda2 + (k-K1)].
// mode 0: out = sigmoid(v)
// mode 1: out = sigmoid(v) * h_epi[row,col]
// mode 2: out = silu(v) = v * sigmoid(v)
// mode 3: out = v
#define BM 128
#define BN 128
#define BK 8
#define TM 8
#define TN 8

__global__ __launch_bounds__(256, 2)
void sgemm_fused(const float* __restrict__ A1, int lda1, int K1,
                 const float* __restrict__ A2, int lda2,
                 const float* __restrict__ W,
                 const float* __restrict__ bias,
                 const float* __restrict__ h_epi,
                 float* __restrict__ out,
                 int K, int N, int mode)
{
    __shared__ float As[BK][BM];
    __shared__ float Bs[BK][BN];

    const int bm  = blockIdx.y * BM;
    const int bn  = blockIdx.x * BN;
    const int tid = threadIdx.x;

    // A tile load: 128 rows x 8 cols, one float4 per thread
    const int arow  = tid >> 1;
    const int acol4 = (tid & 1) * 4;
    // B tile load: 8 rows x 128 cols, one float4 per thread
    const int brow = tid >> 5;
    const int bcol = (tid & 31) * 4;

    const int ty = (tid >> 4) * TM;   // 0..120 step 8
    const int tx = (tid & 15) * TN;   // 0..120 step 8

    unsigned long long acc[TM][TN / 2];
#pragma unroll
    for (int i = 0; i < TM; i++)
#pragma unroll
        for (int j = 0; j < TN / 2; j++) acc[i][j] = 0ULL;

    for (int k0 = 0; k0 < K; k0 += BK) {
        // ---- load A tile (handles the [x | h2] concat; K1 % BK == 0) ----
        {
            const int ga = bm + arow;
            const int ka = k0 + acol4;
            float4 av;
            if (ka < K1)
                av = *(const float4*)(A1 + (long)ga * lda1 + ka);
            else
                av = *(const float4*)(A2 + (long)ga * lda2 + (ka - K1));
            As[acol4 + 0][arow] = av.x;
            As[acol4 + 1][arow] = av.y;
            As[acol4 + 2][arow] = av.z;
            As[acol4 + 3][arow] = av.w;
        }
        // ---- load B tile ----
        {
            float4 bv = *(const float4*)(W + (long)(k0 + brow) * N + (bn + bcol));
            *(float4*)(&Bs[brow][bcol]) = bv;
        }
        __syncthreads();

#pragma unroll
        for (int kk = 0; kk < BK; kk++) {
            float4 a0 = *(const float4*)(&As[kk][ty]);
            float4 a1 = *(const float4*)(&As[kk][ty + 4]);
            float4 b0 = *(const float4*)(&Bs[kk][tx]);
            float4 b1 = *(const float4*)(&Bs[kk][tx + 4]);

            unsigned long long bb[4];
            bb[0] = pack2(b0.x, b0.y);
            bb[1] = pack2(b0.z, b0.w);
            bb[2] = pack2(b1.x, b1.y);
            bb[3] = pack2(b1.z, b1.w);

            float a[8] = {a0.x, a0.y, a0.z, a0.w, a1.x, a1.y, a1.z, a1.w};
#pragma unroll
            for (int i = 0; i < TM; i++) {
                unsigned long long aa = pack2(a[i], a[i]);
#pragma unroll
                for (int j = 0; j < TN / 2; j++) fma2(acc[i][j], aa, bb[j]);
            }
        }
        __syncthreads();
    }

    // ---- epilogue ----
#pragma unroll
    for (int i = 0; i < TM; i++) {
        const int row = bm + ty + i;
#pragma unroll
        for (int j = 0; j < TN / 2; j++) {
            float2 c = unpack2(acc[i][j]);
            const int col = bn + tx + 2 * j;
            float v0 = c.x + bias[col];
            float v1 = c.y + bias[col + 1];
            float r0, r1;
            if (mode == 0) {
                r0 = sigmoidf(v0);
                r1 = sigmoidf(v1);
            } else if (mode == 1) {
                r0 = sigmoidf(v0) * h_epi[(long)row * N + col];
                r1 = sigmoidf(v1) * h_epi[(long)row * N + col + 1];
            } else if (mode == 2) {
                r0 = v0 * sigmoidf(v0);
                r1 = v1 * sigmoidf(v1);
            } else {
                r0 = v0;
                r1 = v1;
            }
            out[(long)row * N + col]     = r0;
            out[(long)row * N + col + 1] = r1;
        }
    }
}

// ---------------- LayerNorm over new_h (row width H_) with fused combine ----------------
// val = (1-u)*h + u*silu(gate)*up + h = h*(2-u) + u*sg*up
__global__ void ln_newh_kernel(const float* __restrict__ u, const float* __restrict__ h,
                               const float* __restrict__ sg, const float* __restrict__ up,
                               const float* __restrict__ gamma, const float* __restrict__ beta,
                               float* __restrict__ out)
{
    const int row = blockIdx.x;
    const int tid = threadIdx.x;
    const int PER = H_ / 256;  // 16
    const long base = (long)row * H_;

    float v[PER];
    float s = 0.f, ss = 0.f;
#pragma unroll
    for (int i = 0; i < PER; i++) {
        const int j = i * 256 + tid;
        const float uu = u[base + j];
        const float hh = h[base + j];
        const float val = hh * (2.f - uu) + uu * sg[base + j] * up[base + j];
        v[i] = val;
        s += val;
        ss += val * val;
    }
    __shared__ float sm[2][8];
#pragma unroll
    for (int o = 16; o > 0; o >>= 1) {
        s  += __shfl_xor_sync(0xffffffffu, s, o);
        ss += __shfl_xor_sync(0xffffffffu, ss, o);
    }
    const int warp = tid >> 5, lane = tid & 31;
    if (lane == 0) { sm[0][warp] = s; sm[1][warp] = ss; }
    __syncthreads();
    float ts = 0.f, tss = 0.f;
#pragma unroll
    for (int w = 0; w < 8; w++) { ts += sm[0][w]; tss += sm[1][w]; }
    const float mean = ts / (float)H_;
    const float var  = tss / (float)H_ - mean * mean;
    const float rstd = rsqrtf(var + LN_EPS);
#pragma unroll
    for (int i = 0; i < PER; i++) {
        const int j = i * 256 + tid;
        out[base + j] = (v[i] - mean) * rstd * gamma[j] + beta[j];
    }
}

// ---------------- LayerNorm over the down projection (row width D_) ----------------
__global__ void ln_out_kernel(const float* __restrict__ in,
                              const float* __restrict__ gamma, const float* __restrict__ beta,
                              float* __restrict__ out)
{
    const int row = blockIdx.x;
    const int tid = threadIdx.x;
    const int PER = D_ / 256;  // 4
    const long base = (long)row * D_;

    float v[PER];
    float s = 0.f, ss = 0.f;
#pragma unroll
    for (int i = 0; i < PER; i++) {
        const int j = i * 256 + tid;
        const float val = in[base + j];
        v[i] = val;
        s += val;
        ss += val * val;
    }
    __shared__ float sm[2][8];
#pragma unroll
    for (int o = 16; o > 0; o >>= 1) {
        s  += __shfl_xor_sync(0xffffffffu, s, o);
        ss += __shfl_xor_sync(0xffffffffu, ss, o);
    }
    const int warp = tid >> 5, lane = tid & 31;
    if (lane == 0) { sm[0][warp] = s; sm[1][warp] = ss; }
    __syncthreads();
    float ts = 0.f, tss = 0.f;
#pragma unroll
    for (int w = 0; w < 8; w++) { ts += sm[0][w]; tss += sm[1][w]; }
    const float mean = ts / (float)D_;
    const float var  = tss / (float)D_ - mean * mean;
    const float rstd = rsqrtf(var + LN_EPS);
#pragma unroll
    for (int i = 0; i < PER; i++) {
        const int j = i * 256 + tid;
        out[base + j] = (v[i] - mean) * rstd * gamma[j] + beta[j];
    }
}

// ---------------- launch ----------------
extern "C" void kernel_launch(void* const* d_in, const int* in_sizes, int n_in,
                              void* d_out, int out_size)
{
    const float* x    = (const float*)d_in[0];
    const float* h    = (const float*)d_in[1];
    const float* W_u  = (const float*)d_in[2];
    const float* b_u  = (const float*)d_in[3];
    const float* W_r  = (const float*)d_in[4];
    const float* b_r  = (const float*)d_in[5];
    const float* W_g  = (const float*)d_in[6];
    const float* b_g  = (const float*)d_in[7];
    const float* W_up = (const float*)d_in[8];
    const float* b_up = (const float*)d_in[9];
    const float* W_d  = (const float*)d_in[10];
    const float* b_d  = (const float*)d_in[11];
    const float* g_h  = (const float*)d_in[12];
    const float* be_h = (const float*)d_in[13];
    const float* g_o  = (const float*)d_in[14];
    const float* be_o = (const float*)d_in[15];

    float* out = (float*)d_out;

    float *pu, *prh, *psg, *pup, *pnh, *pdo;
    cudaGetSymbolAddress((void**)&pu,  g_u);
    cudaGetSymbolAddress((void**)&prh, g_rh);
    cudaGetSymbolAddress((void**)&psg, g_sg);
    cudaGetSymbolAddress((void**)&pup, g_up);
    cudaGetSymbolAddress((void**)&pnh, g_nh);
    cudaGetSymbolAddress((void**)&pdo, g_do);

    // Output layout probe: tuple (out, new_h) flattened -> [B*D | B*H].
    // If d_out only holds `out`, keep new_h in scratch.
    float* newh = (out_size >= B_ * (D_ + H_)) ? (out + (long)B_ * D_) : pnh;

    dim3 blk(256);
    dim3 gBig(H_ / BN, B_ / BM);   // 32 x 8
    dim3 gDown(D_ / BN, B_ / BM);  // 8 x 8

    // u = sigmoid([x|h] @ W_u + b_u)
    sgemm_fused<<<gBig, blk>>>(x, D_, D_, h, H_, W_u, b_u, nullptr, pu, C_, H_, 0);
    // rh = sigmoid([x|h] @ W_r + b_r) * h
    sgemm_fused<<<gBig, blk>>>(x, D_, D_, h, H_, W_r, b_r, h, prh, C_, H_, 1);
    // sg = silu([x|rh] @ W_g + b_g)
    sgemm_fused<<<gBig, blk>>>(x, D_, D_, prh, H_, W_g, b_g, nullptr, psg, C_, H_, 2);
    // up = [x|rh] @ W_up + b_up
    sgemm_fused<<<gBig, blk>>>(x, D_, D_, prh, H_, W_up, b_up, nullptr, pup, C_, H_, 3);
    // new_h = LN(h*(2-u) + u*sg*up)
    ln_newh_kernel<<<B_, blk>>>(pu, h, psg, pup, g_h, be_h, newh);
    // pre-LN out = new_h @ W_d + b_d
    sgemm_fused<<<gDown, blk>>>(newh, H_, H_, nullptr, H_, W_d, b_d, nullptr, pdo, H_, D_, 3);
    // out = LN(...)
    ln_out_kernel<<<B_, blk>>>(pdo, g_o, be_o, out);
}

// round 4
// speedup vs baseline: 2.2567x; 2.2567x over previous
#include <cuda_runtime.h>
#include <cuda_bf16.h>
#include <math.h>
#include <stdint.h>

#define B_ 1024
#define D_ 1024
#define H_ 4096
#define C_ 5120
#define LN_EPS 1e-3f
#define KSLICE_D 4

// ---------------- scratch (device globals: allocation-free) ----------------
__device__ __align__(1024) __nv_bfloat16 g_a1h[B_ * C_], g_a1l[B_ * C_];
__device__ __align__(1024) __nv_bfloat16 g_a2h[B_ * C_], g_a2l[B_ * C_];
__device__ __align__(1024) __nv_bfloat16 g_a3h[B_ * H_], g_a3l[B_ * H_];
__device__ __align__(1024) __nv_bfloat16 g_wb0h[(long)H_ * C_], g_wb0l[(long)H_ * C_];
__device__ __align__(1024) __nv_bfloat16 g_wb1h[(long)H_ * C_], g_wb1l[(long)H_ * C_];
__device__ __align__(1024) __nv_bfloat16 g_wdh[(long)D_ * H_], g_wdl[(long)D_ * H_];
__device__ float g_u [B_ * H_];
__device__ float g_g [B_ * H_];
__device__ float g_up[B_ * H_];
__device__ float g_nh[B_ * H_];
__device__ float g_do[KSLICE_D * B_ * D_];

// ---------------- helpers ----------------
__device__ __forceinline__ uint32_t smem_u32(const void* p) {
    uint32_t a;
    asm("{ .reg .u64 t; cvta.to.shared.u64 t, %1; cvt.u32.u64 %0, t; }" : "=r"(a) : "l"(p));
    return a;
}
__device__ __forceinline__ void cp16(uint32_t dst, const void* src) {
    asm volatile("cp.async.cg.shared.global [%0], [%1], 16;" :: "r"(dst), "l"(src) : "memory");
}
__device__ __forceinline__ void ldsm_x4(uint32_t* r, uint32_t addr) {
    asm volatile("ldmatrix.sync.aligned.m8n8.x4.shared.b16 {%0,%1,%2,%3}, [%4];"
                 : "=r"(r[0]), "=r"(r[1]), "=r"(r[2]), "=r"(r[3]) : "r"(addr));
}
__device__ __forceinline__ void ldsm_x2(uint32_t* r, uint32_t addr) {
    asm volatile("ldmatrix.sync.aligned.m8n8.x2.shared.b16 {%0,%1}, [%2];"
                 : "=r"(r[0]), "=r"(r[1]) : "r"(addr));
}
__device__ __forceinline__ void mma16816(float* c, const uint32_t* a, const uint32_t* b) {
    asm volatile(
        "mma.sync.aligned.m16n8k16.row.col.f32.bf16.bf16.f32 "
        "{%0,%1,%2,%3}, {%4,%5,%6,%7}, {%8,%9}, {%0,%1,%2,%3};"
        : "+f"(c[0]), "+f"(c[1]), "+f"(c[2]), "+f"(c[3])
        : "r"(a[0]), "r"(a[1]), "r"(a[2]), "r"(a[3]), "r"(b[0]), "r"(b[1]));
}
__device__ __forceinline__ void split_bf(float f, __nv_bfloat16& hi, __nv_bfloat16& lo) {
    hi = __float2bfloat16(f);
    lo = __float2bfloat16(f - __bfloat162float(hi));
}
__device__ __forceinline__ float sigm(float x) { return 1.0f / (1.0f + expf(-x)); }

// ---------------- split-bf16 HMMA GEMM ----------------
// C[128,128] tile = A[128,K] @ B^T where B stored [N,K] (K-contiguous), hi/lo pairs.
// 3-term: Ah*Bh + Ah*Bl + Al*Bh accumulated fp32.
// MODE 0: nt < nhalf -> u = sigmoid(v+bias0) f32; else rh = sigmoid(v+bias1)*hmul -> bf16 split into obh/obl concat
// MODE 1: raw v+bias -> fout0 (first) / fout1 (second)
// MODE 2: raw v (no bias) -> fout0 + z*B_*D_   (split-K over gridDim.z)
#define KT 64
#define STG 3
#define STAGE_BYTES 65536u   // 4 tiles of 128x64 bf16 (16KB each)

template<int MODE>
__global__ void __launch_bounds__(256, 1) gemm_hmma(
    const __nv_bfloat16* __restrict__ Ah, const __nv_bfloat16* __restrict__ Al, int ldA,
    const __nv_bfloat16* __restrict__ B0h, const __nv_bfloat16* __restrict__ B0l,
    const __nv_bfloat16* __restrict__ B1h, const __nv_bfloat16* __restrict__ B1l, int ldB,
    const float* __restrict__ bias0, const float* __restrict__ bias1,
    const float* __restrict__ hmul,
    float* __restrict__ fout0, float* __restrict__ fout1,
    __nv_bfloat16* __restrict__ obh, __nv_bfloat16* __restrict__ obl,
    int K, int nhalf, int kslices)
{
    extern __shared__ __align__(1024) char smraw[];
    const uint32_t sb = smem_u32(smraw);

    const int tid = threadIdx.x, lane = tid & 31, wid = tid >> 5;
    const int wm = (wid >> 2) * 64;   // warp M offset (0 / 64)
    const int wn = (wid & 3) * 32;    // warp N offset (0/32/64/96)
    const int nt = blockIdx.x, mt = blockIdx.y;
    const bool second = nt >= nhalf;
    const int ntin = second ? nt - nhalf : nt;
    const __nv_bfloat16* Bh = second ? B1h : B0h;
    const __nv_bfloat16* Bl = second ? B1l : B0l;
    const float* bias = second ? bias1 : bias0;

    const int m0 = mt * 128, n0 = ntin * 128;
    const int Ks = K / kslices;
    const int kbeg = blockIdx.z * Ks;
    const int S = Ks / KT;

    // ---- stage loader: 4 tiles of [128 rows][64 bf16], SW128 swizzled ----
    const int lr = tid >> 1;           // row 0..127
    const int lcb = (tid & 1) * 4;     // chunk base 0 or 4
    auto load_stage = [&](int slot, int kk) {
        const uint32_t dbase = sb + (uint32_t)slot * STAGE_BYTES + (uint32_t)lr * 128;
        const size_t arow = (size_t)(m0 + lr) * ldA + kk;
        const size_t brow = (size_t)(n0 + lr) * ldB + kk;
#pragma unroll
        for (int c = 0; c < 4; c++) {
            const int ch = lcb + c;
            const uint32_t sw = (uint32_t)((ch ^ (lr & 7)) << 4);
            cp16(dbase + sw,          Ah + arow + ch * 8);
            cp16(dbase + 16384 + sw,  Al + arow + ch * 8);
            cp16(dbase + 32768 + sw,  Bh + brow + ch * 8);
            cp16(dbase + 49152 + sw,  Bl + brow + ch * 8);
        }
    };

    // prologue
#pragma unroll
    for (int s = 0; s < STG; s++) {
        if (s < S) load_stage(s, kbeg + s * KT);
        asm volatile("cp.async.commit_group;" ::: "memory");
    }

    float acc[4][4][4];
#pragma unroll
    for (int i = 0; i < 4; i++)
#pragma unroll
        for (int j = 0; j < 4; j++)
#pragma unroll
            for (int e = 0; e < 4; e++) acc[i][j][e] = 0.f;

    for (int ks = 0; ks < S; ks++) {
        asm volatile("cp.async.wait_group 1;" ::: "memory");  // STG-2
        __syncthreads();
        const uint32_t base = sb + (uint32_t)(ks % STG) * STAGE_BYTES;

#pragma unroll
        for (int s = 0; s < 4; s++) {   // 4 k16 steps per 64-wide stage
            uint32_t ah[4][4], al[4][4], bh[4][2], bl[4][2];
#pragma unroll
            for (int i = 0; i < 4; i++) {
                const int row = wm + i * 16 + (lane & 15);
                const uint32_t bcol = (uint32_t)(s * 32 + ((lane >> 4) & 1) * 16);
                const uint32_t off = (uint32_t)row * 128 + (bcol ^ (uint32_t)((row & 7) << 4));
                ldsm_x4(ah[i], base + off);
                ldsm_x4(al[i], base + 16384 + off);
            }
#pragma unroll
            for (int j = 0; j < 4; j++) {
                const int row = wn + j * 8 + (lane & 7);
                const uint32_t bcol = (uint32_t)(s * 32 + ((lane >> 3) & 1) * 16);
                const uint32_t off = (uint32_t)row * 128 + (bcol ^ (uint32_t)((row & 7) << 4));
                ldsm_x2(bh[j], base + 32768 + off);
                ldsm_x2(bl[j], base + 49152 + off);
            }
#pragma unroll
            for (int i = 0; i < 4; i++)
#pragma unroll
                for (int j = 0; j < 4; j++) {
                    mma16816(acc[i][j], ah[i], bh[j]);
                    mma16816(acc[i][j], ah[i], bl[j]);
                    mma16816(acc[i][j], al[i], bh[j]);
                }
        }
        __syncthreads();
        if (ks + STG < S) load_stage(ks % STG, kbeg + (ks + STG) * KT);
        asm volatile("cp.async.commit_group;" ::: "memory");
    }

    // ---- epilogue ----
#pragma unroll
    for (int i = 0; i < 4; i++) {
#pragma unroll
        for (int j = 0; j < 4; j++) {
            const int r0 = m0 + wm + i * 16 + (lane >> 2);
            const int gc = ntin * 128 + wn + j * 8 + 2 * (lane & 3);
#pragma unroll
            for (int half = 0; half < 2; half++) {
                const int row = r0 + half * 8;
                const float v0r = acc[i][j][half * 2];
                const float v1r = acc[i][j][half * 2 + 1];
                if (MODE == 0) {
                    const float v0 = v0r + bias[gc], v1 = v1r + bias[gc + 1];
                    if (!second) {
                        fout0[(long)row * H_ + gc]     = sigm(v0);
                        fout0[(long)row * H_ + gc + 1] = sigm(v1);
                    } else {
                        const float rh0 = sigm(v0) * hmul[(long)row * H_ + gc];
                        const float rh1 = sigm(v1) * hmul[(long)row * H_ + gc + 1];
                        __nv_bfloat16 h0, l0, h1, l1;
                        split_bf(rh0, h0, l0);
                        split_bf(rh1, h1, l1);
                        obh[(long)row * C_ + D_ + gc]     = h0;
                        obl[(long)row * C_ + D_ + gc]     = l0;
                        obh[(long)row * C_ + D_ + gc + 1] = h1;
                        obl[(long)row * C_ + D_ + gc + 1] = l1;
                    }
                } else if (MODE == 1) {
                    float* dst = second ? fout1 : fout0;
                    dst[(long)row * H_ + gc]     = v0r + bias[gc];
                    dst[(long)row * H_ + gc + 1] = v1r + bias[gc + 1];
                } else {
                    float* dst = fout0 + (size_t)blockIdx.z * B_ * D_;
                    dst[(long)row * D_ + gc]     = v0r;
                    dst[(long)row * D_ + gc + 1] = v1r;
                }
            }
        }
    }
}

// ---------------- conversion kernels ----------------
__global__ void conv_a1(const float* __restrict__ x, const float* __restrict__ h,
                        __nv_bfloat16* __restrict__ a1h, __nv_bfloat16* __restrict__ a1l,
                        __nv_bfloat16* __restrict__ a2h, __nv_bfloat16* __restrict__ a2l)
{
    const long i = (long)blockIdx.x * blockDim.x + threadIdx.x;
    if (i >= (long)B_ * C_) return;
    const int row = (int)(i / C_), c = (int)(i % C_);
    const float f = (c < D_) ? x[(long)row * D_ + c] : h[(long)row * H_ + (c - D_)];
    __nv_bfloat16 hi, lo;
    split_bf(f, hi, lo);
    a1h[i] = hi; a1l[i] = lo;
    if (c < D_) { a2h[i] = hi; a2l[i] = lo; }
}

// transpose + split: src [K, N] f32 row-major -> dst [N, K] bf16 hi/lo
__global__ void tconv(const float* __restrict__ src,
                      __nv_bfloat16* __restrict__ dh, __nv_bfloat16* __restrict__ dl,
                      int K, int N)
{
    __shared__ float t[32][33];
    const int kt = blockIdx.y * 32, nb = blockIdx.x * 32;
    const int tx = threadIdx.x, ty = threadIdx.y;
#pragma unroll
    for (int yy = ty; yy < 32; yy += 8)
        t[yy][tx] = src[(long)(kt + yy) * N + nb + tx];
    __syncthreads();
#pragma unroll
    for (int yy = ty; yy < 32; yy += 8) {
        const float f = t[tx][yy];
        __nv_bfloat16 hi, lo;
        split_bf(f, hi, lo);
        const long o = (long)(nb + yy) * K + kt + tx;
        dh[o] = hi; dl[o] = lo;
    }
}

// ---------------- LayerNorm kernels ----------------
__global__ void ln_newh(const float* __restrict__ u, const float* __restrict__ h,
                        const float* __restrict__ g, const float* __restrict__ up,
                        const float* __restrict__ gamma, const float* __restrict__ beta,
                        float* __restrict__ out,
                        __nv_bfloat16* __restrict__ a3h, __nv_bfloat16* __restrict__ a3l)
{
    const int row = blockIdx.x, tid = threadIdx.x;
    const int PER = H_ / 256;
    const long base = (long)row * H_;
    float v[PER];
    float s = 0.f, ss = 0.f;
#pragma unroll
    for (int i = 0; i < PER; i++) {
        const int j = i * 256 + tid;
        const float uu = u[base + j];
        const float gg = g[base + j];
        const float val = h[base + j] * (2.f - uu) + uu * (gg * sigm(gg)) * up[base + j];
        v[i] = val; s += val; ss += val * val;
    }
    __shared__ float sm[2][8];
#pragma unroll
    for (int o = 16; o > 0; o >>= 1) {
        s  += __shfl_xor_sync(0xffffffffu, s, o);
        ss += __shfl_xor_sync(0xffffffffu, ss, o);
    }
    const int warp = tid >> 5, lane = tid & 31;
    if (lane == 0) { sm[0][warp] = s; sm[1][warp] = ss; }
    __syncthreads();
    float ts = 0.f, tss = 0.f;
#pragma unroll
    for (int w = 0; w < 8; w++) { ts += sm[0][w]; tss += sm[1][w]; }
    const float mean = ts / (float)H_;
    const float var  = tss / (float)H_ - mean * mean;
    const float rstd = rsqrtf(var + LN_EPS);
#pragma unroll
    for (int i = 0; i < PER; i++) {
        const int j = i * 256 + tid;
        const float r = (v[i] - mean) * rstd * gamma[j] + beta[j];
        out[base + j] = r;
        __nv_bfloat16 hi, lo;
        split_bf(r, hi, lo);
        a3h[base + j] = hi; a3l[base + j] = lo;
    }
}

// sums KSLICE_D split-K partials + bias, then LayerNorm
__global__ void ln_out(const float* __restrict__ in,
                       const float* __restrict__ bd,
                       const float* __restrict__ gamma, const float* __restrict__ beta,
                       float* __restrict__ out)
{
    const int row = blockIdx.x, tid = threadIdx.x;
    const int PER = D_ / 256;
    const long base = (long)row * D_;
    const long zoff = (long)B_ * D_;
    float v[PER];
    float s = 0.f, ss = 0.f;
#pragma unroll
    for (int i = 0; i < PER; i++) {
        const int j = i * 256 + tid;
        float val = bd[j];
#pragma unroll
        for (int z = 0; z < KSLICE_D; z++) val += in[z * zoff + base + j];
        v[i] = val; s += val; ss += val * val;
    }
    __shared__ float sm[2][8];
#pragma unroll
    for (int o = 16; o > 0; o >>= 1) {
        s  += __shfl_xor_sync(0xffffffffu, s, o);
        ss += __shfl_xor_sync(0xffffffffu, ss, o);
    }
    const int warp = tid >> 5, lane = tid & 31;
    if (lane == 0) { sm[0][warp] = s; sm[1][warp] = ss; }
    __syncthreads();
    float ts = 0.f, tss = 0.f;
#pragma unroll
    for (int w = 0; w < 8; w++) { ts += sm[0][w]; tss += sm[1][w]; }
    const float mean = ts / (float)D_;
    const float var  = tss / (float)D_ - mean * mean;
    const float rstd = rsqrtf(var + LN_EPS);
#pragma unroll
    for (int i = 0; i < PER; i++) {
        const int j = i * 256 + tid;
        out[base + j] = (v[i] - mean) * rstd * gamma[j] + beta[j];
    }
}

// ---------------- host ----------------
extern "C" void kernel_launch(void* const* d_in, const int* in_sizes, int n_in,
                              void* d_out, int out_size)
{
    const float* x    = (const float*)d_in[0];
    const float* h    = (const float*)d_in[1];
    const float* W_u  = (const float*)d_in[2];
    const float* b_u  = (const float*)d_in[3];
    const float* W_r  = (const float*)d_in[4];
    const float* b_r  = (const float*)d_in[5];
    const float* W_g  = (const float*)d_in[6];
    const float* b_g  = (const float*)d_in[7];
    const float* W_up = (const float*)d_in[8];
    const float* b_up = (const float*)d_in[9];
    const float* W_d  = (const float*)d_in[10];
    const float* b_d  = (const float*)d_in[11];
    const float* g_h  = (const float*)d_in[12];
    const float* be_h = (const float*)d_in[13];
    const float* g_o  = (const float*)d_in[14];
    const float* be_o = (const float*)d_in[15];
    float* out = (float*)d_out;

    void *pa1h, *pa1l, *pa2h, *pa2l, *pa3h, *pa3l;
    void *pwb0h, *pwb0l, *pwb1h, *pwb1l, *pwdh, *pwdl;
    float *pu, *pg, *pup, *pnh, *pdo;
    cudaGetSymbolAddress(&pa1h, g_a1h);   cudaGetSymbolAddress(&pa1l, g_a1l);
    cudaGetSymbolAddress(&pa2h, g_a2h);   cudaGetSymbolAddress(&pa2l, g_a2l);
    cudaGetSymbolAddress(&pa3h, g_a3h);   cudaGetSymbolAddress(&pa3l, g_a3l);
    cudaGetSymbolAddress(&pwb0h, g_wb0h); cudaGetSymbolAddress(&pwb0l, g_wb0l);
    cudaGetSymbolAddress(&pwb1h, g_wb1h); cudaGetSymbolAddress(&pwb1l, g_wb1l);
    cudaGetSymbolAddress(&pwdh, g_wdh);   cudaGetSymbolAddress(&pwdl, g_wdl);
    cudaGetSymbolAddress((void**)&pu,  g_u);
    cudaGetSymbolAddress((void**)&pg,  g_g);
    cudaGetSymbolAddress((void**)&pup, g_up);
    cudaGetSymbolAddress((void**)&pnh, g_nh);
    cudaGetSymbolAddress((void**)&pdo, g_do);

    constexpr int SMEM = STG * (int)STAGE_BYTES;  // 196608
    cudaFuncSetAttribute((const void*)gemm_hmma<0>, cudaFuncAttributeMaxDynamicSharedMemorySize, SMEM);
    cudaFuncSetAttribute((const void*)gemm_hmma<1>, cudaFuncAttributeMaxDynamicSharedMemorySize, SMEM);
    cudaFuncSetAttribute((const void*)gemm_hmma<2>, cudaFuncAttributeMaxDynamicSharedMemorySize, SMEM);

    float* newh = (out_size >= B_ * (D_ + H_)) ? (out + (long)B_ * D_) : pnh;

    const long nA1 = (long)B_ * C_;
    conv_a1<<<(unsigned)((nA1 + 255) / 256), 256>>>(
        x, h, (__nv_bfloat16*)pa1h, (__nv_bfloat16*)pa1l,
        (__nv_bfloat16*)pa2h, (__nv_bfloat16*)pa2l);

    dim3 tblk(32, 8);
    tconv<<<dim3(H_ / 32, C_ / 32), tblk>>>(W_u, (__nv_bfloat16*)pwb0h, (__nv_bfloat16*)pwb0l, C_, H_);
    tconv<<<dim3(H_ / 32, C_ / 32), tblk>>>(W_r, (__nv_bfloat16*)pwb1h, (__nv_bfloat16*)pwb1l, C_, H_);
    tconv<<<dim3(D_ / 32, H_ / 32), tblk>>>(W_d, (__nv_bfloat16*)pwdh, (__nv_bfloat16*)pwdl, H_, D_);

    // u = sigmoid([x|h]Wu+bu);  rh = sigmoid([x|h]Wr+br)*h -> bf16 split into A2
    gemm_hmma<0><<<dim3(64, 8, 1), 256, SMEM>>>(
        (const __nv_bfloat16*)pa1h, (const __nv_bfloat16*)pa1l, C_,
        (const __nv_bfloat16*)pwb0h, (const __nv_bfloat16*)pwb0l,
        (const __nv_bfloat16*)pwb1h, (const __nv_bfloat16*)pwb1l, C_,
        b_u, b_r, h, pu, nullptr,
        (__nv_bfloat16*)pa2h, (__nv_bfloat16*)pa2l, C_, 32, 1);

    tconv<<<dim3(H_ / 32, C_ / 32), tblk>>>(W_g,  (__nv_bfloat16*)pwb0h, (__nv_bfloat16*)pwb0l, C_, H_);
    tconv<<<dim3(H_ / 32, C_ / 32), tblk>>>(W_up, (__nv_bfloat16*)pwb1h, (__nv_bfloat16*)pwb1l, C_, H_);

    // g = [x|rh]Wg+bg ; up = [x|rh]Wup+bup (raw f32)
    gemm_hmma<1><<<dim3(64, 8, 1), 256, SMEM>>>(
        (const __nv_bfloat16*)pa2h, (const __nv_bfloat16*)pa2l, C_,
        (const __nv_bfloat16*)pwb0h, (const __nv_bfloat16*)pwb0l,
        (const __nv_bfloat16*)pwb1h, (const __nv_bfloat16*)pwb1l, C_,
        b_g, b_up, nullptr, pg, pup, nullptr, nullptr, C_, 32, 1);

    ln_newh<<<B_, 256>>>(pu, h, pg, pup, g_h, be_h, newh,
                         (__nv_bfloat16*)pa3h, (__nv_bfloat16*)pa3l);

    // down: new_h @ W_d (split-K x4, raw partials)
    gemm_hmma<2><<<dim3(8, 8, KSLICE_D), 256, SMEM>>>(
        (const __nv_bfloat16*)pa3h, (const __nv_bfloat16*)pa3l, H_,
        (const __nv_bfloat16*)pwdh, (const __nv_bfloat16*)pwdl,
        (const __nv_bfloat16*)pwdh, (const __nv_bfloat16*)pwdl, H_,
        b_d, b_d, nullptr, pdo, nullptr, nullptr, nullptr, H_, 1000, KSLICE_D);

    ln_out<<<B_, 256>>>(pdo, b_d, g_o, be_o, out);
}

// round 5
// speedup vs baseline: 2.3283x; 1.0317x over previous
#include <cuda_runtime.h>
#include <cuda_bf16.h>
#include <math.h>
#include <stdint.h>

#define B_ 1024
#define D_ 1024
#define H_ 4096
#define C_ 5120
#define LN_EPS 1e-3f
#define KSLICE_D 4

// ---------------- scratch (device globals: allocation-free) ----------------
__device__ __align__(1024) __nv_bfloat16 g_a1h[B_ * C_], g_a1l[B_ * C_];
__device__ __align__(1024) __nv_bfloat16 g_a2h[B_ * C_], g_a2l[B_ * C_];
__device__ __align__(1024) __nv_bfloat16 g_a3h[B_ * H_], g_a3l[B_ * H_];
__device__ __align__(1024) __nv_bfloat16 g_wuh[(long)H_ * C_],  g_wul[(long)H_ * C_];
__device__ __align__(1024) __nv_bfloat16 g_wrh[(long)H_ * C_],  g_wrl[(long)H_ * C_];
__device__ __align__(1024) __nv_bfloat16 g_wgh[(long)H_ * C_],  g_wgl[(long)H_ * C_];
__device__ __align__(1024) __nv_bfloat16 g_wph[(long)H_ * C_],  g_wpl[(long)H_ * C_];
__device__ __align__(1024) __nv_bfloat16 g_wdh[(long)D_ * H_],  g_wdl[(long)D_ * H_];
__device__ float g_u [B_ * H_];
__device__ float g_g [B_ * H_];
__device__ float g_up[B_ * H_];
__device__ float g_nh[B_ * H_];
__device__ float g_do[KSLICE_D * B_ * D_];

// ---------------- helpers ----------------
__device__ __forceinline__ uint32_t smem_u32(const void* p) {
    uint32_t a;
    asm("{ .reg .u64 t; cvta.to.shared.u64 t, %1; cvt.u32.u64 %0, t; }" : "=r"(a) : "l"(p));
    return a;
}
__device__ __forceinline__ void cp16(uint32_t dst, const void* src) {
    asm volatile("cp.async.cg.shared.global [%0], [%1], 16;" :: "r"(dst), "l"(src) : "memory");
}
__device__ __forceinline__ void ldsm_x4(uint32_t* r, uint32_t addr) {
    asm volatile("ldmatrix.sync.aligned.m8n8.x4.shared.b16 {%0,%1,%2,%3}, [%4];"
                 : "=r"(r[0]), "=r"(r[1]), "=r"(r[2]), "=r"(r[3]) : "r"(addr));
}
__device__ __forceinline__ void ldsm_x2(uint32_t* r, uint32_t addr) {
    asm volatile("ldmatrix.sync.aligned.m8n8.x2.shared.b16 {%0,%1}, [%2];"
                 : "=r"(r[0]), "=r"(r[1]) : "r"(addr));
}
__device__ __forceinline__ void mma16816(float* c, const uint32_t* a, const uint32_t* b) {
    asm volatile(
        "mma.sync.aligned.m16n8k16.row.col.f32.bf16.bf16.f32 "
        "{%0,%1,%2,%3}, {%4,%5,%6,%7}, {%8,%9}, {%0,%1,%2,%3};"
        : "+f"(c[0]), "+f"(c[1]), "+f"(c[2]), "+f"(c[3])
        : "r"(a[0]), "r"(a[1]), "r"(a[2]), "r"(a[3]), "r"(b[0]), "r"(b[1]));
}
__device__ __forceinline__ void split_bf(float f, __nv_bfloat16& hi, __nv_bfloat16& lo) {
    hi = __float2bfloat16(f);
    lo = __float2bfloat16(f - __bfloat162float(hi));
}
__device__ __forceinline__ float sigm(float x) { return 1.0f / (1.0f + expf(-x)); }

// ---------------- split-bf16 HMMA GEMM ----------------
#define KT 64
#define STG 3
#define STAGE_BYTES 65536u   // 4 tiles of 128x64 bf16 (16KB each)

template<int MODE>
__global__ void __launch_bounds__(256, 1) gemm_hmma(
    const __nv_bfloat16* __restrict__ Ah, const __nv_bfloat16* __restrict__ Al, int ldA,
    const __nv_bfloat16* __restrict__ B0h, const __nv_bfloat16* __restrict__ B0l,
    const __nv_bfloat16* __restrict__ B1h, const __nv_bfloat16* __restrict__ B1l, int ldB,
    const float* __restrict__ bias0, const float* __restrict__ bias1,
    const float* __restrict__ hmul,
    float* __restrict__ fout0, float* __restrict__ fout1,
    __nv_bfloat16* __restrict__ obh, __nv_bfloat16* __restrict__ obl,
    int K, int nhalf, int kslices)
{
    extern __shared__ __align__(1024) char smraw[];
    const uint32_t sb = smem_u32(smraw);

    const int tid = threadIdx.x, lane = tid & 31, wid = tid >> 5;
    const int wm = (wid >> 2) * 64;   // warp M offset (0 / 64)
    const int wn = (wid & 3) * 32;    // warp N offset (0/32/64/96)
    const int nt = blockIdx.x, mt = blockIdx.y;
    const bool second = nt >= nhalf;
    const int ntin = second ? nt - nhalf : nt;
    const __nv_bfloat16* Bh = second ? B1h : B0h;
    const __nv_bfloat16* Bl = second ? B1l : B0l;
    const float* bias = second ? bias1 : bias0;

    const int m0 = mt * 128, n0 = ntin * 128;
    const int Ks = K / kslices;
    const int kbeg = blockIdx.z * Ks;
    const int S = Ks / KT;

    // ---- stage loader: 4 tiles of [128 rows][64 bf16], xor-swizzled ----
    const int lr = tid >> 1;           // row 0..127
    const int lcb = (tid & 1) * 4;     // chunk base 0 or 4
    auto load_stage = [&](int slot, int kk) {
        const uint32_t dbase = sb + (uint32_t)slot * STAGE_BYTES + (uint32_t)lr * 128;
        const size_t arow = (size_t)(m0 + lr) * ldA + kk;
        const size_t brow = (size_t)(n0 + lr) * ldB + kk;
#pragma unroll
        for (int c = 0; c < 4; c++) {
            const int ch = lcb + c;
            const uint32_t sw = (uint32_t)((ch ^ (lr & 7)) << 4);
            cp16(dbase + sw,          Ah + arow + ch * 8);
            cp16(dbase + 16384 + sw,  Al + arow + ch * 8);
            cp16(dbase + 32768 + sw,  Bh + brow + ch * 8);
            cp16(dbase + 49152 + sw,  Bl + brow + ch * 8);
        }
    };

    // prologue
#pragma unroll
    for (int s = 0; s < STG; s++) {
        if (s < S) load_stage(s, kbeg + s * KT);
        asm volatile("cp.async.commit_group;" ::: "memory");
    }

    float acc[4][4][4];
#pragma unroll
    for (int i = 0; i < 4; i++)
#pragma unroll
        for (int j = 0; j < 4; j++)
#pragma unroll
            for (int e = 0; e < 4; e++) acc[i][j][e] = 0.f;

    for (int ks = 0; ks < S; ks++) {
        asm volatile("cp.async.wait_group 2;" ::: "memory");
        __syncthreads();
        const uint32_t base = sb + (uint32_t)(ks % STG) * STAGE_BYTES;

#pragma unroll
        for (int s = 0; s < 4; s++) {   // 4 k16 steps per 64-wide stage
            uint32_t ah[4][4], al[4][4], bh[4][2], bl[4][2];
#pragma unroll
            for (int i = 0; i < 4; i++) {
                const int row = wm + i * 16 + (lane & 15);
                const uint32_t bcol = (uint32_t)(s * 32 + ((lane >> 4) & 1) * 16);
                const uint32_t off = (uint32_t)row * 128 + (bcol ^ (uint32_t)((row & 7) << 4));
                ldsm_x4(ah[i], base + off);
                ldsm_x4(al[i], base + 16384 + off);
            }
#pragma unroll
            for (int j = 0; j < 4; j++) {
                const int row = wn + j * 8 + (lane & 7);
                const uint32_t bcol = (uint32_t)(s * 32 + ((lane >> 3) & 1) * 16);
                const uint32_t off = (uint32_t)row * 128 + (bcol ^ (uint32_t)((row & 7) << 4));
                ldsm_x2(bh[j], base + 32768 + off);
                ldsm_x2(bl[j], base + 49152 + off);
            }
            // term-outer ordering: 16 independent accumulators between reuse
#pragma unroll
            for (int i = 0; i < 4; i++)
#pragma unroll
                for (int j = 0; j < 4; j++) mma16816(acc[i][j], ah[i], bh[j]);
#pragma unroll
            for (int i = 0; i < 4; i++)
#pragma unroll
                for (int j = 0; j < 4; j++) mma16816(acc[i][j], ah[i], bl[j]);
#pragma unroll
            for (int i = 0; i < 4; i++)
#pragma unroll
                for (int j = 0; j < 4; j++) mma16816(acc[i][j], al[i], bh[j]);
        }
        __syncthreads();
        if (ks + STG < S) load_stage(ks % STG, kbeg + (ks + STG) * KT);
        asm volatile("cp.async.commit_group;" ::: "memory");
    }

    // ---- epilogue ----
#pragma unroll
    for (int i = 0; i < 4; i++) {
#pragma unroll
        for (int j = 0; j < 4; j++) {
            const int r0 = m0 + wm + i * 16 + (lane >> 2);
            const int gc = ntin * 128 + wn + j * 8 + 2 * (lane & 3);
#pragma unroll
            for (int half = 0; half < 2; half++) {
                const int row = r0 + half * 8;
                const float v0r = acc[i][j][half * 2];
                const float v1r = acc[i][j][half * 2 + 1];
                if (MODE == 0) {
                    const float v0 = v0r + bias[gc], v1 = v1r + bias[gc + 1];
                    if (!second) {
                        fout0[(long)row * H_ + gc]     = sigm(v0);
                        fout0[(long)row * H_ + gc + 1] = sigm(v1);
                    } else {
                        const float rh0 = sigm(v0) * hmul[(long)row * H_ + gc];
                        const float rh1 = sigm(v1) * hmul[(long)row * H_ + gc + 1];
                        __nv_bfloat16 h0, l0, h1, l1;
                        split_bf(rh0, h0, l0);
                        split_bf(rh1, h1, l1);
                        obh[(long)row * C_ + D_ + gc]     = h0;
                        obl[(long)row * C_ + D_ + gc]     = l0;
                        obh[(long)row * C_ + D_ + gc + 1] = h1;
                        obl[(long)row * C_ + D_ + gc + 1] = l1;
                    }
                } else if (MODE == 1) {
                    float* dst = second ? fout1 : fout0;
                    dst[(long)row * H_ + gc]     = v0r + bias[gc];
                    dst[(long)row * H_ + gc + 1] = v1r + bias[gc + 1];
                } else {
                    float* dst = fout0 + (size_t)blockIdx.z * B_ * D_;
                    dst[(long)row * D_ + gc]     = v0r;
                    dst[(long)row * D_ + gc + 1] = v1r;
                }
            }
        }
    }
}

// ---------------- conversion kernels ----------------
// A1 = split([x | h]) (vectorized); also write the x-part of A2
__global__ void conv_a1(const float* __restrict__ x, const float* __restrict__ h,
                        __nv_bfloat16* __restrict__ a1h, __nv_bfloat16* __restrict__ a1l,
                        __nv_bfloat16* __restrict__ a2h, __nv_bfloat16* __restrict__ a2l)
{
    const long i4 = (long)blockIdx.x * blockDim.x + threadIdx.x;
    if (i4 >= (long)B_ * C_ / 4) return;
    const int row = (int)(i4 / (C_ / 4));
    const int c = (int)(i4 % (C_ / 4)) * 4;
    float4 f;
    if (c < D_) f = *(const float4*)(x + (long)row * D_ + c);
    else        f = *(const float4*)(h + (long)row * H_ + (c - D_));
    __nv_bfloat16 h0, l0, h1, l1, h2, l2, h3, l3;
    split_bf(f.x, h0, l0); split_bf(f.y, h1, l1);
    split_bf(f.z, h2, l2); split_bf(f.w, h3, l3);
    __nv_bfloat162 hv0 = {h0, h1}, hv1 = {h2, h3};
    __nv_bfloat162 lv0 = {l0, l1}, lv1 = {l2, l3};
    const long o = (long)row * C_ + c;
    *(uint2*)(a1h + o) = make_uint2(*(uint32_t*)&hv0, *(uint32_t*)&hv1);
    *(uint2*)(a1l + o) = make_uint2(*(uint32_t*)&lv0, *(uint32_t*)&lv1);
    if (c < D_) {
        *(uint2*)(a2h + o) = make_uint2(*(uint32_t*)&hv0, *(uint32_t*)&hv1);
        *(uint2*)(a2l + o) = make_uint2(*(uint32_t*)&lv0, *(uint32_t*)&lv1);
    }
}

// transpose + split: src [K, N] f32 -> dst [N, K] bf16 hi/lo.
// Tiles: 64 (K) x 32 (N). 128B-coalesced loads and 128B-coalesced 16B stores.
__global__ void tconv(const float* __restrict__ src,
                      __nv_bfloat16* __restrict__ dh, __nv_bfloat16* __restrict__ dl,
                      int K, int N)
{
    __shared__ float t[64][33];
    const int kt = blockIdx.y * 64, nb = blockIdx.x * 32;
    const int tid = threadIdx.x;

    // load 64 rows x 32 floats
    {
        const int tx = tid & 31, r0 = tid >> 5;
#pragma unroll
        for (int r = r0; r < 64; r += 8)
            t[r][tx] = src[(long)(kt + r) * N + nb + tx];
    }
    __syncthreads();

    // each thread: one output row segment of 8 bf16 (16B) for hi and lo
    const int n  = tid >> 3;          // 0..31
    const int k8 = (tid & 7) * 8;     // 0..56
    __nv_bfloat162 hv[4], lv[4];
#pragma unroll
    for (int i = 0; i < 4; i++) {
        const float f0 = t[k8 + 2 * i][n], f1 = t[k8 + 2 * i + 1][n];
        __nv_bfloat16 h0, l0, h1, l1;
        split_bf(f0, h0, l0);
        split_bf(f1, h1, l1);
        hv[i] = {h0, h1};
        lv[i] = {l0, l1};
    }
    const long o = (long)(nb + n) * K + kt + k8;
    *(uint4*)(dh + o) = make_uint4(*(uint32_t*)&hv[0], *(uint32_t*)&hv[1],
                                   *(uint32_t*)&hv[2], *(uint32_t*)&hv[3]);
    *(uint4*)(dl + o) = make_uint4(*(uint32_t*)&lv[0], *(uint32_t*)&lv[1],
                                   *(uint32_t*)&lv[2], *(uint32_t*)&lv[3]);
}

// ---------------- LayerNorm kernels ----------------
__global__ void ln_newh(const float* __restrict__ u, const float* __restrict__ h,
                        const float* __restrict__ g, const float* __restrict__ up,
                        const float* __restrict__ gamma, const float* __restrict__ beta,
                        float* __restrict__ out,
                        __nv_bfloat16* __restrict__ a3h, __nv_bfloat16* __restrict__ a3l)
{
    const int row = blockIdx.x, tid = threadIdx.x;
    const int PER = H_ / 256;
    const long base = (long)row * H_;
    float v[PER];
    float s = 0.f, ss = 0.f;
#pragma unroll
    for (int i = 0; i < PER; i++) {
        const int j = i * 256 + tid;
        const float uu = u[base + j];
        const float gg = g[base + j];
        const float val = h[base + j] * (2.f - uu) + uu * (gg * sigm(gg)) * up[base + j];
        v[i] = val; s += val; ss += val * val;
    }
    __shared__ float sm[2][8];
#pragma unroll
    for (int o = 16; o > 0; o >>= 1) {
        s  += __shfl_xor_sync(0xffffffffu, s, o);
        ss += __shfl_xor_sync(0xffffffffu, ss, o);
    }
    const int warp = tid >> 5, lane = tid & 31;
    if (lane == 0) { sm[0][warp] = s; sm[1][warp] = ss; }
    __syncthreads();
    float ts = 0.f, tss = 0.f;
#pragma unroll
    for (int w = 0; w < 8; w++) { ts += sm[0][w]; tss += sm[1][w]; }
    const float mean = ts / (float)H_;
    const float var  = tss / (float)H_ - mean * mean;
    const float rstd = rsqrtf(var + LN_EPS);
#pragma unroll
    for (int i = 0; i < PER; i++) {
        const int j = i * 256 + tid;
        const float r = (v[i] - mean) * rstd * gamma[j] + beta[j];
        out[base + j] = r;
        __nv_bfloat16 hi, lo;
        split_bf(r, hi, lo);
        a3h[base + j] = hi; a3l[base + j] = lo;
    }
}

__global__ void ln_out(const float* __restrict__ in,
                       const float* __restrict__ bd,
                       const float* __restrict__ gamma, const float* __restrict__ beta,
                       float* __restrict__ out)
{
    const int row = blockIdx.x, tid = threadIdx.x;
    const int PER = D_ / 256;
    const long base = (long)row * D_;
    const long zoff = (long)B_ * D_;
    float v[PER];
    float s = 0.f, ss = 0.f;
#pragma unroll
    for (int i = 0; i < PER; i++) {
        const int j = i * 256 + tid;
        float val = bd[j];
#pragma unroll
        for (int z = 0; z < KSLICE_D; z++) val += in[z * zoff + base + j];
        v[i] = val; s += val; ss += val * val;
    }
    __shared__ float sm[2][8];
#pragma unroll
    for (int o = 16; o > 0; o >>= 1) {
        s  += __shfl_xor_sync(0xffffffffu, s, o);
        ss += __shfl_xor_sync(0xffffffffu, ss, o);
    }
    const int warp = tid >> 5, lane = tid & 31;
    if (lane == 0) { sm[0][warp] = s; sm[1][warp] = ss; }
    __syncthreads();
    float ts = 0.f, tss = 0.f;
#pragma unroll
    for (int w = 0; w < 8; w++) { ts += sm[0][w]; tss += sm[1][w]; }
    const float mean = ts / (float)D_;
    const float var  = tss / (float)D_ - mean * mean;
    const float rstd = rsqrtf(var + LN_EPS);
#pragma unroll
    for (int i = 0; i < PER; i++) {
        const int j = i * 256 + tid;
        out[base + j] = (v[i] - mean) * rstd * gamma[j] + beta[j];
    }
}

// ---------------- host ----------------
extern "C" void kernel_launch(void* const* d_in, const int* in_sizes, int n_in,
                              void* d_out, int out_size)
{
    const float* x    = (const float*)d_in[0];
    const float* h    = (const float*)d_in[1];
    const float* W_u  = (const float*)d_in[2];
    const float* b_u  = (const float*)d_in[3];
    const float* W_r  = (const float*)d_in[4];
    const float* b_r  = (const float*)d_in[5];
    const float* W_g  = (const float*)d_in[6];
    const float* b_g  = (const float*)d_in[7];
    const float* W_up = (const float*)d_in[8];
    const float* b_up = (const float*)d_in[9];
    const float* W_d  = (const float*)d_in[10];
    const float* b_d  = (const float*)d_in[11];
    const float* g_h  = (const float*)d_in[12];
    const float* be_h = (const float*)d_in[13];
    const float* g_o  = (const float*)d_in[14];
    const float* be_o = (const float*)d_in[15];
    float* out = (float*)d_out;

    void *pa1h, *pa1l, *pa2h, *pa2l, *pa3h, *pa3l;
    void *pwuh, *pwul, *pwrh, *pwrl, *pwgh, *pwgl, *pwph, *pwpl, *pwdh, *pwdl;
    float *pu, *pg, *pup, *pnh, *pdo;
    cudaGetSymbolAddress(&pa1h, g_a1h); cudaGetSymbolAddress(&pa1l, g_a1l);
    cudaGetSymbolAddress(&pa2h, g_a2h); cudaGetSymbolAddress(&pa2l, g_a2l);
    cudaGetSymbolAddress(&pa3h, g_a3h); cudaGetSymbolAddress(&pa3l, g_a3l);
    cudaGetSymbolAddress(&pwuh, g_wuh); cudaGetSymbolAddress(&pwul, g_wul);
    cudaGetSymbolAddress(&pwrh, g_wrh); cudaGetSymbolAddress(&pwrl, g_wrl);
    cudaGetSymbolAddress(&pwgh, g_wgh); cudaGetSymbolAddress(&pwgl, g_wgl);
    cudaGetSymbolAddress(&pwph, g_wph); cudaGetSymbolAddress(&pwpl, g_wpl);
    cudaGetSymbolAddress(&pwdh, g_wdh); cudaGetSymbolAddress(&pwdl, g_wdl);
    cudaGetSymbolAddress((void**)&pu,  g_u);
    cudaGetSymbolAddress((void**)&pg,  g_g);
    cudaGetSymbolAddress((void**)&pup, g_up);
    cudaGetSymbolAddress((void**)&pnh, g_nh);
    cudaGetSymbolAddress((void**)&pdo, g_do);

    constexpr int SMEM = STG * (int)STAGE_BYTES;  // 196608
    cudaFuncSetAttribute((const void*)gemm_hmma<0>, cudaFuncAttributeMaxDynamicSharedMemorySize, SMEM);
    cudaFuncSetAttribute((const void*)gemm_hmma<1>, cudaFuncAttributeMaxDynamicSharedMemorySize, SMEM);
    cudaFuncSetAttribute((const void*)gemm_hmma<2>, cudaFuncAttributeMaxDynamicSharedMemorySize, SMEM);

    float* newh = (out_size >= B_ * (D_ + H_)) ? (out + (long)B_ * D_) : pnh;

    conv_a1<<<(unsigned)(((long)B_ * C_ / 4 + 255) / 256), 256>>>(
        x, h, (__nv_bfloat16*)pa1h, (__nv_bfloat16*)pa1l,
        (__nv_bfloat16*)pa2h, (__nv_bfloat16*)pa2l);

    tconv<<<dim3(H_ / 32, C_ / 64), 256>>>(W_u,  (__nv_bfloat16*)pwuh, (__nv_bfloat16*)pwul, C_, H_);
    tconv<<<dim3(H_ / 32, C_ / 64), 256>>>(W_r,  (__nv_bfloat16*)pwrh, (__nv_bfloat16*)pwrl, C_, H_);
    tconv<<<dim3(H_ / 32, C_ / 64), 256>>>(W_g,  (__nv_bfloat16*)pwgh, (__nv_bfloat16*)pwgl, C_, H_);
    tconv<<<dim3(H_ / 32, C_ / 64), 256>>>(W_up, (__nv_bfloat16*)pwph, (__nv_bfloat16*)pwpl, C_, H_);
    tconv<<<dim3(D_ / 32, H_ / 64), 256>>>(W_d,  (__nv_bfloat16*)pwdh, (__nv_bfloat16*)pwdl, H_, D_);

    // u = sigmoid([x|h]Wu+bu);  rh = sigmoid([x|h]Wr+br)*h -> bf16 split into A2
    gemm_hmma<0><<<dim3(64, 8, 1), 256, SMEM>>>(
        (const __nv_bfloat16*)pa1h, (const __nv_bfloat16*)pa1l, C_,
        (const __nv_bfloat16*)pwuh, (const __nv_bfloat16*)pwul,
        (const __nv_bfloat16*)pwrh, (const __nv_bfloat16*)pwrl, C_,
        b_u, b_r, h, pu, nullptr,
        (__nv_bfloat16*)pa2h, (__nv_bfloat16*)pa2l, C_, 32, 1);

    // g = [x|rh]Wg+bg ; up = [x|rh]Wup+bup (raw f32)
    gemm_hmma<1><<<dim3(64, 8, 1), 256, SMEM>>>(
        (const __nv_bfloat16*)pa2h, (const __nv_bfloat16*)pa2l, C_,
        (const __nv_bfloat16*)pwgh, (const __nv_bfloat16*)pwgl,
        (const __nv_bfloat16*)pwph, (const __nv_bfloat16*)pwpl, C_,
        b_g, b_up, nullptr, pg, pup, nullptr, nullptr, C_, 32, 1);

    ln_newh<<<B_, 256>>>(pu, h, pg, pup, g_h, be_h, newh,
                         (__nv_bfloat16*)pa3h, (__nv_bfloat16*)pa3l);

    // down: new_h @ W_d (split-K x4, raw partials)
    gemm_hmma<2><<<dim3(8, 8, KSLICE_D), 256, SMEM>>>(
        (const __nv_bfloat16*)pa3h, (const __nv_bfloat16*)pa3l, H_,
        (const __nv_bfloat16*)pwdh, (const __nv_bfloat16*)pwdl,
        (const __nv_bfloat16*)pwdh, (const __nv_bfloat16*)pwdl, H_,
        b_d, b_d, nullptr, pdo, nullptr, nullptr, nullptr, H_, 1000, KSLICE_D);

    ln_out<<<B_, 256>>>(pdo, b_d, g_o, be_o, out);
}

// round 6
// speedup vs baseline: 2.3800x; 1.0222x over previous
#include <cuda_runtime.h>
#include <cuda_bf16.h>
#include <math.h>
#include <stdint.h>

#define B_ 1024
#define D_ 1024
#define H_ 4096
#define C_ 5120
#define LN_EPS 1e-3f
#define KSLICE_D 4

// ---------------- scratch (device globals: allocation-free) ----------------
__device__ __align__(1024) __nv_bfloat16 g_a1h[B_ * C_], g_a1l[B_ * C_];
__device__ __align__(1024) __nv_bfloat16 g_a2h[B_ * C_], g_a2l[B_ * C_];
__device__ __align__(1024) __nv_bfloat16 g_a3h[B_ * H_], g_a3l[B_ * H_];
__device__ __align__(1024) __nv_bfloat16 g_wuh[(long)H_ * C_],  g_wul[(long)H_ * C_];
__device__ __align__(1024) __nv_bfloat16 g_wrh[(long)H_ * C_],  g_wrl[(long)H_ * C_];
__device__ __align__(1024) __nv_bfloat16 g_wgh[(long)H_ * C_],  g_wgl[(long)H_ * C_];
__device__ __align__(1024) __nv_bfloat16 g_wph[(long)H_ * C_],  g_wpl[(long)H_ * C_];
__device__ __align__(1024) __nv_bfloat16 g_wdh[(long)D_ * H_],  g_wdl[(long)D_ * H_];
__device__ float g_u [B_ * H_];
__device__ float g_g [B_ * H_];
__device__ float g_up[B_ * H_];
__device__ float g_nh[B_ * H_];
__device__ float g_do[KSLICE_D * B_ * D_];

// ---------------- helpers ----------------
__device__ __forceinline__ uint32_t smem_u32(const void* p) {
    uint32_t a;
    asm("{ .reg .u64 t; cvta.to.shared.u64 t, %1; cvt.u32.u64 %0, t; }" : "=r"(a) : "l"(p));
    return a;
}
__device__ __forceinline__ void cp16(uint32_t dst, const void* src) {
    asm volatile("cp.async.cg.shared.global [%0], [%1], 16;" :: "r"(dst), "l"(src) : "memory");
}
__device__ __forceinline__ void ldsm_x4(uint32_t* r, uint32_t addr) {
    asm volatile("ldmatrix.sync.aligned.m8n8.x4.shared.b16 {%0,%1,%2,%3}, [%4];"
                 : "=r"(r[0]), "=r"(r[1]), "=r"(r[2]), "=r"(r[3]) : "r"(addr));
}
__device__ __forceinline__ void mma16816(float* c, const uint32_t* a, uint32_t b0, uint32_t b1) {
    asm volatile(
        "mma.sync.aligned.m16n8k16.row.col.f32.bf16.bf16.f32 "
        "{%0,%1,%2,%3}, {%4,%5,%6,%7}, {%8,%9}, {%0,%1,%2,%3};"
        : "+f"(c[0]), "+f"(c[1]), "+f"(c[2]), "+f"(c[3])
        : "r"(a[0]), "r"(a[1]), "r"(a[2]), "r"(a[3]), "r"(b0), "r"(b1));
}
__device__ __forceinline__ void split_bf(float f, __nv_bfloat16& hi, __nv_bfloat16& lo) {
    hi = __float2bfloat16(f);
    lo = __float2bfloat16(f - __bfloat162float(hi));
}
__device__ __forceinline__ float sigm(float x) { return 1.0f / (1.0f + expf(-x)); }

// swizzled address inside a [128 rows][32 bf16] tile (64B rows, 16B chunks)
__device__ __forceinline__ uint32_t sw_addr(uint32_t tbase, int row, int cb) {
    return tbase + (uint32_t)row * 64u + (uint32_t)((cb ^ ((row >> 1) & 3)) << 4);
}

// ---------------- split-bf16 HMMA GEMM (2 CTAs/SM) ----------------
#define KT 32
#define STG 3
#define STAGE_BYTES 32768u   // 4 tiles of 128x32 bf16 (8KB each)
// tile offsets within a stage: Ah 0, Al 8192, Bh 16384, Bl 24576

template<int MODE>
__global__ void __launch_bounds__(256, 2) gemm_hmma(
    const __nv_bfloat16* __restrict__ Ah, const __nv_bfloat16* __restrict__ Al, int ldA,
    const __nv_bfloat16* __restrict__ B0h, const __nv_bfloat16* __restrict__ B0l,
    const __nv_bfloat16* __restrict__ B1h, const __nv_bfloat16* __restrict__ B1l, int ldB,
    const float* __restrict__ bias0, const float* __restrict__ bias1,
    const float* __restrict__ hmul,
    float* __restrict__ fout0, float* __restrict__ fout1,
    __nv_bfloat16* __restrict__ obh, __nv_bfloat16* __restrict__ obl,
    int K, int nhalf, int kslices)
{
    extern __shared__ __align__(1024) char smraw[];
    const uint32_t sb = smem_u32(smraw);

    const int tid = threadIdx.x, lane = tid & 31, wid = tid >> 5;
    const int wm = (wid >> 2) * 64;   // warp M offset (0 / 64)
    const int wn = (wid & 3) * 32;    // warp N offset (0/32/64/96)
    const int nt = blockIdx.x, mt = blockIdx.y;
    const bool second = nt >= nhalf;
    const int ntin = second ? nt - nhalf : nt;
    const __nv_bfloat16* Bhp = second ? B1h : B0h;
    const __nv_bfloat16* Blp = second ? B1l : B0l;
    const float* bias = second ? bias1 : bias0;

    const int m0 = mt * 128, n0 = ntin * 128;
    const int Ks = K / kslices;
    const int kbeg = blockIdx.z * Ks;
    const int S = Ks / KT;

    // ---- stage loader: 4 tiles of [128 rows][32 bf16], swizzled ----
    const int lr  = tid >> 1;            // row 0..127
    const int lcb = (tid & 1) * 2;       // chunk base 0 or 2
    auto load_stage = [&](int slot, int kk) {
        const uint32_t tb = sb + (uint32_t)slot * STAGE_BYTES;
        const size_t arow = (size_t)(m0 + lr) * ldA + kk;
        const size_t brow = (size_t)(n0 + lr) * ldB + kk;
#pragma unroll
        for (int c = 0; c < 2; c++) {
            const int cb = lcb + c;
            const uint32_t sw = sw_addr(tb, lr, cb);
            cp16(sw,          Ah  + arow + cb * 8);
            cp16(sw + 8192,   Al  + arow + cb * 8);
            cp16(sw + 16384,  Bhp + brow + cb * 8);
            cp16(sw + 24576,  Blp + brow + cb * 8);
        }
    };

    // prologue
#pragma unroll
    for (int s = 0; s < STG; s++) {
        if (s < S) load_stage(s, kbeg + s * KT);
        asm volatile("cp.async.commit_group;" ::: "memory");
    }

    float acc[4][4][4];
#pragma unroll
    for (int i = 0; i < 4; i++)
#pragma unroll
        for (int j = 0; j < 4; j++)
#pragma unroll
            for (int e = 0; e < 4; e++) acc[i][j][e] = 0.f;

    for (int ks = 0; ks < S; ks++) {
        asm volatile("cp.async.wait_group 2;" ::: "memory");
        __syncthreads();
        const uint32_t base = sb + (uint32_t)(ks % STG) * STAGE_BYTES;

#pragma unroll
        for (int s = 0; s < 2; s++) {   // 2 k16 steps per 32-wide stage
            const int acb = s * 2 + ((lane >> 4) & 1);   // A/B ldsm chunk for this lane
            // --- A hi fragments + B hi fragments, term hh ---
            uint32_t ah[4][4];
#pragma unroll
            for (int i = 0; i < 4; i++)
                ldsm_x4(ah[i], sw_addr(base, wm + i * 16 + (lane & 15), acb));
            uint32_t bh[2][4];
#pragma unroll
            for (int jp = 0; jp < 2; jp++)
                ldsm_x4(bh[jp], sw_addr(base + 16384, wn + jp * 16 + (lane & 15), acb));
            // b-frag for column j: {b[j>>1][j&1], b[j>>1][2|(j&1)]}
#pragma unroll
            for (int i = 0; i < 4; i++)
#pragma unroll
                for (int j = 0; j < 4; j++)
                    mma16816(acc[i][j], ah[i], bh[j >> 1][j & 1], bh[j >> 1][2 | (j & 1)]);
            // --- B lo fragments, term h*l ---
            uint32_t bl[2][4];
#pragma unroll
            for (int jp = 0; jp < 2; jp++)
                ldsm_x4(bl[jp], sw_addr(base + 24576, wn + jp * 16 + (lane & 15), acb));
#pragma unroll
            for (int i = 0; i < 4; i++)
#pragma unroll
                for (int j = 0; j < 4; j++)
                    mma16816(acc[i][j], ah[i], bl[j >> 1][j & 1], bl[j >> 1][2 | (j & 1)]);
            // --- A lo fragments, term l*h ---
            uint32_t al[4][4];
#pragma unroll
            for (int i = 0; i < 4; i++)
                ldsm_x4(al[i], sw_addr(base + 8192, wm + i * 16 + (lane & 15), acb));
#pragma unroll
            for (int i = 0; i < 4; i++)
#pragma unroll
                for (int j = 0; j < 4; j++)
                    mma16816(acc[i][j], al[i], bh[j >> 1][j & 1], bh[j >> 1][2 | (j & 1)]);
        }
        __syncthreads();
        if (ks + STG < S) load_stage(ks % STG, kbeg + (ks + STG) * KT);
        asm volatile("cp.async.commit_group;" ::: "memory");
    }

    // ---- epilogue ----
#pragma unroll
    for (int i = 0; i < 4; i++) {
#pragma unroll
        for (int j = 0; j < 4; j++) {
            const int r0 = m0 + wm + i * 16 + (lane >> 2);
            const int gc = ntin * 128 + wn + j * 8 + 2 * (lane & 3);
#pragma unroll
            for (int half = 0; half < 2; half++) {
                const int row = r0 + half * 8;
                const float v0r = acc[i][j][half * 2];
                const float v1r = acc[i][j][half * 2 + 1];
                if (MODE == 0) {
                    const float v0 = v0r + bias[gc], v1 = v1r + bias[gc + 1];
                    if (!second) {
                        fout0[(long)row * H_ + gc]     = sigm(v0);
                        fout0[(long)row * H_ + gc + 1] = sigm(v1);
                    } else {
                        const float rh0 = sigm(v0) * hmul[(long)row * H_ + gc];
                        const float rh1 = sigm(v1) * hmul[(long)row * H_ + gc + 1];
                        __nv_bfloat16 h0, l0, h1, l1;
                        split_bf(rh0, h0, l0);
                        split_bf(rh1, h1, l1);
                        obh[(long)row * C_ + D_ + gc]     = h0;
                        obl[(long)row * C_ + D_ + gc]     = l0;
                        obh[(long)row * C_ + D_ + gc + 1] = h1;
                        obl[(long)row * C_ + D_ + gc + 1] = l1;
                    }
                } else if (MODE == 1) {
                    float* dst = second ? fout1 : fout0;
                    dst[(long)row * H_ + gc]     = v0r + bias[gc];
                    dst[(long)row * H_ + gc + 1] = v1r + bias[gc + 1];
                } else {
                    float* dst = fout0 + (size_t)blockIdx.z * B_ * D_;
                    dst[(long)row * D_ + gc]     = v0r;
                    dst[(long)row * D_ + gc + 1] = v1r;
                }
            }
        }
    }
}

// ---------------- conversion kernels ----------------
__global__ void conv_a1(const float* __restrict__ x, const float* __restrict__ h,
                        __nv_bfloat16* __restrict__ a1h, __nv_bfloat16* __restrict__ a1l,
                        __nv_bfloat16* __restrict__ a2h, __nv_bfloat16* __restrict__ a2l)
{
    const long i4 = (long)blockIdx.x * blockDim.x + threadIdx.x;
    if (i4 >= (long)B_ * C_ / 4) return;
    const int row = (int)(i4 / (C_ / 4));
    const int c = (int)(i4 % (C_ / 4)) * 4;
    float4 f;
    if (c < D_) f = *(const float4*)(x + (long)row * D_ + c);
    else        f = *(const float4*)(h + (long)row * H_ + (c - D_));
    __nv_bfloat16 h0, l0, h1, l1, h2, l2, h3, l3;
    split_bf(f.x, h0, l0); split_bf(f.y, h1, l1);
    split_bf(f.z, h2, l2); split_bf(f.w, h3, l3);
    __nv_bfloat162 hv0 = {h0, h1}, hv1 = {h2, h3};
    __nv_bfloat162 lv0 = {l0, l1}, lv1 = {l2, l3};
    const long o = (long)row * C_ + c;
    *(uint2*)(a1h + o) = make_uint2(*(uint32_t*)&hv0, *(uint32_t*)&hv1);
    *(uint2*)(a1l + o) = make_uint2(*(uint32_t*)&lv0, *(uint32_t*)&lv1);
    if (c < D_) {
        *(uint2*)(a2h + o) = make_uint2(*(uint32_t*)&hv0, *(uint32_t*)&hv1);
        *(uint2*)(a2l + o) = make_uint2(*(uint32_t*)&lv0, *(uint32_t*)&lv1);
    }
}

// batched transpose + split for the 4 big weights: src [C_,H_] f32 -> dst [H_,C_] bf16 hi/lo
__global__ void tconv4(const float* __restrict__ s0, const float* __restrict__ s1,
                       const float* __restrict__ s2, const float* __restrict__ s3,
                       __nv_bfloat16* __restrict__ d0h, __nv_bfloat16* __restrict__ d0l,
                       __nv_bfloat16* __restrict__ d1h, __nv_bfloat16* __restrict__ d1l,
                       __nv_bfloat16* __restrict__ d2h, __nv_bfloat16* __restrict__ d2l,
                       __nv_bfloat16* __restrict__ d3h, __nv_bfloat16* __restrict__ d3l)
{
    const int z = blockIdx.z;
    const float* src = z == 0 ? s0 : z == 1 ? s1 : z == 2 ? s2 : s3;
    __nv_bfloat16* dh = z == 0 ? d0h : z == 1 ? d1h : z == 2 ? d2h : d3h;
    __nv_bfloat16* dl = z == 0 ? d0l : z == 1 ? d1l : z == 2 ? d2l : d3l;
    const int K = C_, N = H_;

    __shared__ float t[64][33];
    const int kt = blockIdx.y * 64, nb = blockIdx.x * 32;
    const int tid = threadIdx.x;

    // load 64 rows x 32 floats as float4
    {
        const int c4 = (tid & 7) * 4, r0 = tid >> 3;   // 32 rows per pass
#pragma unroll
        for (int p = 0; p < 2; p++) {
            const int r = r0 + p * 32;
            const float4 f = *(const float4*)(src + (long)(kt + r) * N + nb + c4);
            t[r][c4] = f.x; t[r][c4 + 1] = f.y; t[r][c4 + 2] = f.z; t[r][c4 + 3] = f.w;
        }
    }
    __syncthreads();

    const int n  = tid >> 3;
    const int k8 = (tid & 7) * 8;
    __nv_bfloat162 hv[4], lv[4];
#pragma unroll
    for (int i = 0; i < 4; i++) {
        const float f0 = t[k8 + 2 * i][n], f1 = t[k8 + 2 * i + 1][n];
        __nv_bfloat16 h0, l0, h1, l1;
        split_bf(f0, h0, l0);
        split_bf(f1, h1, l1);
        hv[i] = {h0, h1};
        lv[i] = {l0, l1};
    }
    const long o = (long)(nb + n) * K + kt + k8;
    *(uint4*)(dh + o) = make_uint4(*(uint32_t*)&hv[0], *(uint32_t*)&hv[1],
                                   *(uint32_t*)&hv[2], *(uint32_t*)&hv[3]);
    *(uint4*)(dl + o) = make_uint4(*(uint32_t*)&lv[0], *(uint32_t*)&lv[1],
                                   *(uint32_t*)&lv[2], *(uint32_t*)&lv[3]);
}

// single transpose for W_d: src [H_,D_] -> dst [D_,H_]
__global__ void tconv(const float* __restrict__ src,
                      __nv_bfloat16* __restrict__ dh, __nv_bfloat16* __restrict__ dl,
                      int K, int N)
{
    __shared__ float t[64][33];
    const int kt = blockIdx.y * 64, nb = blockIdx.x * 32;
    const int tid = threadIdx.x;
    {
        const int c4 = (tid & 7) * 4, r0 = tid >> 3;
#pragma unroll
        for (int p = 0; p < 2; p++) {
            const int r = r0 + p * 32;
            const float4 f = *(const float4*)(src + (long)(kt + r) * N + nb + c4);
            t[r][c4] = f.x; t[r][c4 + 1] = f.y; t[r][c4 + 2] = f.z; t[r][c4 + 3] = f.w;
        }
    }
    __syncthreads();
    const int n  = tid >> 3;
    const int k8 = (tid & 7) * 8;
    __nv_bfloat162 hv[4], lv[4];
#pragma unroll
    for (int i = 0; i < 4; i++) {
        const float f0 = t[k8 + 2 * i][n], f1 = t[k8 + 2 * i + 1][n];
        __nv_bfloat16 h0, l0, h1, l1;
        split_bf(f0, h0, l0);
        split_bf(f1, h1, l1);
        hv[i] = {h0, h1};
        lv[i] = {l0, l1};
    }
    const long o = (long)(nb + n) * K + kt + k8;
    *(uint4*)(dh + o) = make_uint4(*(uint32_t*)&hv[0], *(uint32_t*)&hv[1],
                                   *(uint32_t*)&hv[2], *(uint32_t*)&hv[3]);
    *(uint4*)(dl + o) = make_uint4(*(uint32_t*)&lv[0], *(uint32_t*)&lv[1],
                                   *(uint32_t*)&lv[2], *(uint32_t*)&lv[3]);
}

// ---------------- LayerNorm kernels ----------------
__global__ void ln_newh(const float* __restrict__ u, const float* __restrict__ h,
                        const float* __restrict__ g, const float* __restrict__ up,
                        const float* __restrict__ gamma, const float* __restrict__ beta,
                        float* __restrict__ out,
                        __nv_bfloat16* __restrict__ a3h, __nv_bfloat16* __restrict__ a3l)
{
    const int row = blockIdx.x, tid = threadIdx.x;
    const int PER = H_ / 256;
    const long base = (long)row * H_;
    float v[PER];
    float s = 0.f, ss = 0.f;
#pragma unroll
    for (int i = 0; i < PER; i++) {
        const int j = i * 256 + tid;
        const float uu = u[base + j];
        const float gg = g[base + j];
        const float val = h[base + j] * (2.f - uu) + uu * (gg * sigm(gg)) * up[base + j];
        v[i] = val; s += val; ss += val * val;
    }
    __shared__ float sm[2][8];
#pragma unroll
    for (int o = 16; o > 0; o >>= 1) {
        s  += __shfl_xor_sync(0xffffffffu, s, o);
        ss += __shfl_xor_sync(0xffffffffu, ss, o);
    }
    const int warp = tid >> 5, lane = tid & 31;
    if (lane == 0) { sm[0][warp] = s; sm[1][warp] = ss; }
    __syncthreads();
    float ts = 0.f, tss = 0.f;
#pragma unroll
    for (int w = 0; w < 8; w++) { ts += sm[0][w]; tss += sm[1][w]; }
    const float mean = ts / (float)H_;
    const float var  = tss / (float)H_ - mean * mean;
    const float rstd = rsqrtf(var + LN_EPS);
#pragma unroll
    for (int i = 0; i < PER; i++) {
        const int j = i * 256 + tid;
        const float r = (v[i] - mean) * rstd * gamma[j] + beta[j];
        out[base + j] = r;
        __nv_bfloat16 hi, lo;
        split_bf(r, hi, lo);
        a3h[base + j] = hi; a3l[base + j] = lo;
    }
}

__global__ void ln_out(const float* __restrict__ in,
                       const float* __restrict__ bd,
                       const float* __restrict__ gamma, const float* __restrict__ beta,
                       float* __restrict__ out)
{
    const int row = blockIdx.x, tid = threadIdx.x;
    const int PER = D_ / 256;
    const long base = (long)row * D_;
    const long zoff = (long)B_ * D_;
    float v[PER];
    float s = 0.f, ss = 0.f;
#pragma unroll
    for (int i = 0; i < PER; i++) {
        const int j = i * 256 + tid;
        float val = bd[j];
#pragma unroll
        for (int z = 0; z < KSLICE_D; z++) val += in[z * zoff + base + j];
        v[i] = val; s += val; ss += val * val;
    }
    __shared__ float sm[2][8];
#pragma unroll
    for (int o = 16; o > 0; o >>= 1) {
        s  += __shfl_xor_sync(0xffffffffu, s, o);
        ss += __shfl_xor_sync(0xffffffffu, ss, o);
    }
    const int warp = tid >> 5, lane = tid & 31;
    if (lane == 0) { sm[0][warp] = s; sm[1][warp] = ss; }
    __syncthreads();
    float ts = 0.f, tss = 0.f;
#pragma unroll
    for (int w = 0; w < 8; w++) { ts += sm[0][w]; tss += sm[1][w]; }
    const float mean = ts / (float)D_;
    const float var  = tss / (float)D_ - mean * mean;
    const float rstd = rsqrtf(var + LN_EPS);
#pragma unroll
    for (int i = 0; i < PER; i++) {
        const int j = i * 256 + tid;
        out[base + j] = (v[i] - mean) * rstd * gamma[j] + beta[j];
    }
}

// ---------------- host ----------------
extern "C" void kernel_launch(void* const* d_in, const int* in_sizes, int n_in,
                              void* d_out, int out_size)
{
    const float* x    = (const float*)d_in[0];
    const float* h    = (const float*)d_in[1];
    const float* W_u  = (const float*)d_in[2];
    const float* b_u  = (const float*)d_in[3];
    const float* W_r  = (const float*)d_in[4];
    const float* b_r  = (const float*)d_in[5];
    const float* W_g  = (const float*)d_in[6];
    const float* b_g  = (const float*)d_in[7];
    const float* W_up = (const float*)d_in[8];
    const float* b_up = (const float*)d_in[9];
    const float* W_d  = (const float*)d_in[10];
    const float* b_d  = (const float*)d_in[11];
    const float* g_h  = (const float*)d_in[12];
    const float* be_h = (const float*)d_in[13];
    const float* g_o  = (const float*)d_in[14];
    const float* be_o = (const float*)d_in[15];
    float* out = (float*)d_out;

    void *pa1h, *pa1l, *pa2h, *pa2l, *pa3h, *pa3l;
    void *pwuh, *pwul, *pwrh, *pwrl, *pwgh, *pwgl, *pwph, *pwpl, *pwdh, *pwdl;
    float *pu, *pg, *pup, *pnh, *pdo;
    cudaGetSymbolAddress(&pa1h, g_a1h); cudaGetSymbolAddress(&pa1l, g_a1l);
    cudaGetSymbolAddress(&pa2h, g_a2h); cudaGetSymbolAddress(&pa2l, g_a2l);
    cudaGetSymbolAddress(&pa3h, g_a3h); cudaGetSymbolAddress(&pa3l, g_a3l);
    cudaGetSymbolAddress(&pwuh, g_wuh); cudaGetSymbolAddress(&pwul, g_wul);
    cudaGetSymbolAddress(&pwrh, g_wrh); cudaGetSymbolAddress(&pwrl, g_wrl);
    cudaGetSymbolAddress(&pwgh, g_wgh); cudaGetSymbolAddress(&pwgl, g_wgl);
    cudaGetSymbolAddress(&pwph, g_wph); cudaGetSymbolAddress(&pwpl, g_wpl);
    cudaGetSymbolAddress(&pwdh, g_wdh); cudaGetSymbolAddress(&pwdl, g_wdl);
    cudaGetSymbolAddress((void**)&pu,  g_u);
    cudaGetSymbolAddress((void**)&pg,  g_g);
    cudaGetSymbolAddress((void**)&pup, g_up);
    cudaGetSymbolAddress((void**)&pnh, g_nh);
    cudaGetSymbolAddress((void**)&pdo, g_do);

    constexpr int SMEM = STG * (int)STAGE_BYTES;  // 98304 -> 2 CTAs/SM
    cudaFuncSetAttribute((const void*)gemm_hmma<0>, cudaFuncAttributeMaxDynamicSharedMemorySize, SMEM);
    cudaFuncSetAttribute((const void*)gemm_hmma<1>, cudaFuncAttributeMaxDynamicSharedMemorySize, SMEM);
    cudaFuncSetAttribute((const void*)gemm_hmma<2>, cudaFuncAttributeMaxDynamicSharedMemorySize, SMEM);

    float* newh = (out_size >= B_ * (D_ + H_)) ? (out + (long)B_ * D_) : pnh;

    conv_a1<<<(unsigned)(((long)B_ * C_ / 4 + 255) / 256), 256>>>(
        x, h, (__nv_bfloat16*)pa1h, (__nv_bfloat16*)pa1l,
        (__nv_bfloat16*)pa2h, (__nv_bfloat16*)pa2l);

    tconv4<<<dim3(H_ / 32, C_ / 64, 4), 256>>>(
        W_u, W_r, W_g, W_up,
        (__nv_bfloat16*)pwuh, (__nv_bfloat16*)pwul,
        (__nv_bfloat16*)pwrh, (__nv_bfloat16*)pwrl,
        (__nv_bfloat16*)pwgh, (__nv_bfloat16*)pwgl,
        (__nv_bfloat16*)pwph, (__nv_bfloat16*)pwpl);
    tconv<<<dim3(D_ / 32, H_ / 64), 256>>>(W_d, (__nv_bfloat16*)pwdh, (__nv_bfloat16*)pwdl, H_, D_);

    // u = sigmoid([x|h]Wu+bu);  rh = sigmoid([x|h]Wr+br)*h -> bf16 split into A2
    gemm_hmma<0><<<dim3(64, 8, 1), 256, SMEM>>>(
        (const __nv_bfloat16*)pa1h, (const __nv_bfloat16*)pa1l, C_,
        (const __nv_bfloat16*)pwuh, (const __nv_bfloat16*)pwul,
        (const __nv_bfloat16*)pwrh, (const __nv_bfloat16*)pwrl, C_,
        b_u, b_r, h, pu, nullptr,
        (__nv_bfloat16*)pa2h, (__nv_bfloat16*)pa2l, C_, 32, 1);

    // g = [x|rh]Wg+bg ; up = [x|rh]Wup+bup (raw f32)
    gemm_hmma<1><<<dim3(64, 8, 1), 256, SMEM>>>(
        (const __nv_bfloat16*)pa2h, (const __nv_bfloat16*)pa2l, C_,
        (const __nv_bfloat16*)pwgh, (const __nv_bfloat16*)pwgl,
        (const __nv_bfloat16*)pwph, (const __nv_bfloat16*)pwpl, C_,
        b_g, b_up, nullptr, pg, pup, nullptr, nullptr, C_, 32, 1);

    ln_newh<<<B_, 256>>>(pu, h, pg, pup, g_h, be_h, newh,
                         (__nv_bfloat16*)pa3h, (__nv_bfloat16*)pa3l);

    // down: new_h @ W_d (split-K x4, raw partials)
    gemm_hmma<2><<<dim3(8, 8, KSLICE_D), 256, SMEM>>>(
        (const __nv_bfloat16*)pa3h, (const __nv_bfloat16*)pa3l, H_,
        (const __nv_bfloat16*)pwdh, (const __nv_bfloat16*)pwdl,
        (const __nv_bfloat16*)pwdh, (const __nv_bfloat16*)pwdl, H_,
        b_d, b_d, nullptr, pdo, nullptr, nullptr, nullptr, H_, 1000, KSLICE_D);

    ln_out<<<B_, 256>>>(pdo, b_d, g_o, be_o, out);
}